// round 7
// baseline (speedup 1.0000x reference)
#include <cuda_runtime.h>
#include <math.h>

// Problem shape (fixed by the dataset):
//   t: [16, 256, 128, 128] fp32
//   w_reduce: [256, 1024], b_reduce: [256]
//   w_expand: [1024, 256], b_expand: [1024]
// Output: same shape as t.

#define NB   16
#define NC   256
#define NSQ  256
#define NC4  1024         // 4*C
#define IMG_F4 4096       // 128*128/4 float4 per (b,c) image

// Scratch (allocation-free rule: __device__ globals)
__device__ float g_means[NB * NC4];   // layout: [b][q*C + c]
__device__ float g_z    [NB * NSQ];   // layout: [b][j]
__device__ float g_gate [NB * NC4];   // layout: [b][q*C + c]

// ---------------------------------------------------------------------------
// Kernel 1: per-(b,c) quadrant means. (Measured 41.5us @ 82.9% DRAM — keep.)
// ---------------------------------------------------------------------------
__global__ __launch_bounds__(256) void quad_means_kernel(const float* __restrict__ t)
{
    const int img = blockIdx.x;                 // b*C + c
    const int tid = threadIdx.x;
    const float4* __restrict__ p =
        reinterpret_cast<const float4*>(t) + (size_t)img * IMG_F4;

    float topS = 0.f, botS = 0.f;
#pragma unroll
    for (int k = 0; k < 16; ++k) {
        float4 v = p[tid + k * 256];
        float s = (v.x + v.y) + (v.z + v.w);
        if (k < 8) topS += s; else botS += s;
    }

    const bool right = (tid & 31) >= 16;

    __shared__ float sm[4 * 256];
    sm[0 * 256 + tid] = right ? 0.f : topS;   // q0: top-left
    sm[1 * 256 + tid] = right ? topS : 0.f;   // q1: top-right
    sm[2 * 256 + tid] = right ? 0.f : botS;   // q2: bot-left
    sm[3 * 256 + tid] = right ? botS : 0.f;   // q3: bot-right
    __syncthreads();

#pragma unroll
    for (int st = 128; st > 0; st >>= 1) {
        if (tid < st) {
#pragma unroll
            for (int q = 0; q < 4; ++q)
                sm[q * 256 + tid] += sm[q * 256 + tid + st];
        }
        __syncthreads();
    }

    if (tid < 4) {
        const int b = img >> 8;
        const int c = img & 255;
        g_means[b * NC4 + tid * NC + c] = sm[tid * 256] * (1.0f / 4096.0f);
    }
}

// ---------------------------------------------------------------------------
// Kernel 2a: z = mish(means @ w_reduce^T + b_reduce), all batches per CTA.
// Grid 32 CTAs x 256 thr. Warp w owns output j = cta*8 + w. Its w_reduce row
// (1024 fp32) is loaded ONCE into registers (8 coalesced float4 per lane),
// then dotted against all 16 batches' means held in shared (64KB).
// Every weight byte is read exactly once across the grid.
// ---------------------------------------------------------------------------
__global__ __launch_bounds__(256) void fc1_kernel(
    const float* __restrict__ w_reduce, const float* __restrict__ b_reduce)
{
    const int tid  = threadIdx.x;
    const int warp = tid >> 5;
    const int lane = tid & 31;

    __shared__ float4 sm_m[NB * 256];     // all means: 16 x 1024 fp32 = 64KB
    {
        const float4* __restrict__ mp = reinterpret_cast<const float4*>(g_means);
#pragma unroll
        for (int i = 0; i < 16; ++i)
            sm_m[tid + i * 256] = mp[tid + i * 256];
    }
    __syncthreads();

    const int j = blockIdx.x * 8 + warp;
    const float4* __restrict__ w =
        reinterpret_cast<const float4*>(w_reduce + (size_t)j * NC4);

    float4 wr[8];
#pragma unroll
    for (int i = 0; i < 8; ++i)
        wr[i] = w[lane + 32 * i];

    const float bj = b_reduce[j];

#pragma unroll
    for (int b = 0; b < NB; ++b) {
        float acc = 0.f;
#pragma unroll
        for (int i = 0; i < 8; ++i) {
            float4 mv = sm_m[b * 256 + lane + 32 * i];
            acc += wr[i].x * mv.x + wr[i].y * mv.y + wr[i].z * mv.z + wr[i].w * mv.w;
        }
#pragma unroll
        for (int o = 16; o > 0; o >>= 1)
            acc += __shfl_xor_sync(0xFFFFFFFFu, acc, o);
        if (lane == 0) {
            float x = acc + bj;
            float sp = (x > 20.0f) ? x : log1pf(expf(x));
            g_z[b * NSQ + j] = x * tanhf(sp);
        }
    }
}

// ---------------------------------------------------------------------------
// Kernel 2b: gate = sigmoid(z @ w_expand^T + b_expand), all batches per CTA.
// Grid 32 CTAs x 256 thr. Warp w owns 4 outputs j = cta*32 + w*4 + jj.
// Each row (256 fp32) loaded once (2 float4/lane), dotted vs 16 batches'
// z in shared (16KB). Weights read exactly once across the grid.
// ---------------------------------------------------------------------------
__global__ __launch_bounds__(256) void fc2_kernel(
    const float* __restrict__ w_expand, const float* __restrict__ b_expand)
{
    const int tid  = threadIdx.x;
    const int warp = tid >> 5;
    const int lane = tid & 31;

    __shared__ float4 sm_z[NB * 64];      // all z: 16 x 256 fp32 = 16KB
    {
        const float4* __restrict__ zp = reinterpret_cast<const float4*>(g_z);
#pragma unroll
        for (int i = 0; i < 4; ++i)
            sm_z[tid + i * 256] = zp[tid + i * 256];
    }
    __syncthreads();

#pragma unroll
    for (int jj = 0; jj < 4; ++jj) {
        const int j = blockIdx.x * 32 + warp * 4 + jj;
        const float4* __restrict__ w =
            reinterpret_cast<const float4*>(w_expand + (size_t)j * NSQ);
        float4 w0 = w[lane];
        float4 w1 = w[lane + 32];
        const float bj = b_expand[j];

#pragma unroll
        for (int b = 0; b < NB; ++b) {
            float4 z0 = sm_z[b * 64 + lane];
            float4 z1 = sm_z[b * 64 + lane + 32];
            float acc = w0.x * z0.x + w0.y * z0.y + w0.z * z0.z + w0.w * z0.w
                      + w1.x * z1.x + w1.y * z1.y + w1.z * z1.z + w1.w * z1.w;
#pragma unroll
            for (int o = 16; o > 0; o >>= 1)
                acc += __shfl_xor_sync(0xFFFFFFFFu, acc, o);
            if (lane == 0)
                g_gate[b * NC4 + j] = 1.0f / (1.0f + expf(-acc - bj));
        }
    }
}

// ---------------------------------------------------------------------------
// Kernel 3: out = t * gate. 4 float4 per thread, strided by 256 within a
// 1024-float4 block. 1024 | 4096 so a CTA never crosses an image; the four
// accesses of one thread share (b, c, quadrant): rows span a 32-aligned
// 32-row window (same vertical half), col4 = tid&31 fixed (same horizontal
// half). Gate load + index math once per 4 elements; 4 loads in flight.
// ---------------------------------------------------------------------------
__global__ __launch_bounds__(256) void apply_gate_kernel(
    const float* __restrict__ t, float* __restrict__ out)
{
    const int base = blockIdx.x * 1024 + threadIdx.x;   // float4 index

    const int img    = base >> 12;
    const int within = base & (IMG_F4 - 1);
    const int row    = within >> 5;
    const int col4   = within & 31;
    const int q      = ((row >= 64) ? 2 : 0) | ((col4 >= 16) ? 1 : 0);
    const int b      = img >> 8;
    const int c      = img & 255;

    const float gv = __ldg(&g_gate[b * NC4 + q * NC + c]);

    const float4* __restrict__ tp = reinterpret_cast<const float4*>(t);
    float4* __restrict__ op       = reinterpret_cast<float4*>(out);

    float4 v0 = __ldcs(tp + base);
    float4 v1 = __ldcs(tp + base + 256);
    float4 v2 = __ldcs(tp + base + 512);
    float4 v3 = __ldcs(tp + base + 768);

    v0.x *= gv; v0.y *= gv; v0.z *= gv; v0.w *= gv;
    v1.x *= gv; v1.y *= gv; v1.z *= gv; v1.w *= gv;
    v2.x *= gv; v2.y *= gv; v2.z *= gv; v2.w *= gv;
    v3.x *= gv; v3.y *= gv; v3.z *= gv; v3.w *= gv;

    __stcs(op + base,       v0);
    __stcs(op + base + 256, v1);
    __stcs(op + base + 512, v2);
    __stcs(op + base + 768, v3);
}

// ---------------------------------------------------------------------------
extern "C" void kernel_launch(void* const* d_in, const int* in_sizes, int n_in,
                              void* d_out, int out_size)
{
    const float* t        = (const float*)d_in[0];
    const float* w_reduce = (const float*)d_in[1];
    const float* b_reduce = (const float*)d_in[2];
    const float* w_expand = (const float*)d_in[3];
    const float* b_expand = (const float*)d_in[4];
    float* out            = (float*)d_out;

    // Pass 1: quadrant means (4096 CTAs) — measured 41.5us @ 82.9% DRAM
    quad_means_kernel<<<NB * NC, 256>>>(t);

    // FC chain — weights read exactly once across the grid
    fc1_kernel<<<32, 256>>>(w_reduce, b_reduce);
    fc2_kernel<<<32, 256>>>(w_expand, b_expand);

    // Pass 2: gated multiply. 16M float4 / (256 thr * 4 f4) = 16384 CTAs
    const int total_f4 = NB * NC * IMG_F4;   // 16777216
    apply_gate_kernel<<<total_f4 / 1024, 256>>>(t, out);
}

// round 8
// speedup vs baseline: 1.1084x; 1.1084x over previous
#include <cuda_runtime.h>
#include <math.h>

// Problem shape (fixed by the dataset):
//   t: [16, 256, 128, 128] fp32
//   w_reduce: [256, 1024], b_reduce: [256]
//   w_expand: [1024, 256], b_expand: [1024]
// Output: same shape as t.

#define NB   16
#define NC   256
#define NSQ  256
#define NC4  1024         // 4*C
#define IMG_F4 4096       // 128*128/4 float4 per (b,c) image

// Scratch (allocation-free rule: __device__ globals)
__device__ float g_means[NB * NC4];   // layout: [b][q*C + c]
__device__ float g_z    [NB * NSQ];   // layout: [b][j]
__device__ float g_gate [NB * NC4];   // layout: [b][q*C + c]

// ---------------------------------------------------------------------------
// Kernel 1: per-(b,c) quadrant means. (Measured 41.5us @ 82.9% DRAM — keep.)
// ---------------------------------------------------------------------------
__global__ __launch_bounds__(256) void quad_means_kernel(const float* __restrict__ t)
{
    const int img = blockIdx.x;                 // b*C + c
    const int tid = threadIdx.x;
    const float4* __restrict__ p =
        reinterpret_cast<const float4*>(t) + (size_t)img * IMG_F4;

    float topS = 0.f, botS = 0.f;
#pragma unroll
    for (int k = 0; k < 16; ++k) {
        float4 v = p[tid + k * 256];
        float s = (v.x + v.y) + (v.z + v.w);
        if (k < 8) topS += s; else botS += s;
    }

    const bool right = (tid & 31) >= 16;

    __shared__ float sm[4 * 256];
    sm[0 * 256 + tid] = right ? 0.f : topS;   // q0: top-left
    sm[1 * 256 + tid] = right ? topS : 0.f;   // q1: top-right
    sm[2 * 256 + tid] = right ? 0.f : botS;   // q2: bot-left
    sm[3 * 256 + tid] = right ? botS : 0.f;   // q3: bot-right
    __syncthreads();

#pragma unroll
    for (int st = 128; st > 0; st >>= 1) {
        if (tid < st) {
#pragma unroll
            for (int q = 0; q < 4; ++q)
                sm[q * 256 + tid] += sm[q * 256 + tid + st];
        }
        __syncthreads();
    }

    if (tid < 4) {
        const int b = img >> 8;
        const int c = img & 255;
        g_means[b * NC4 + tid * NC + c] = sm[tid * 256] * (1.0f / 4096.0f);
    }
}

// ---------------------------------------------------------------------------
// Kernel 2a: z = mish(means @ w_reduce^T + b_reduce).
// PDL: weight rows loaded into registers BEFORE the dependency sync (they
// don't depend on quad_means), overlapping with quad_means' tail.
// Grid 32 x 256. Warp w owns output j = cta*8 + w; keeps 16 per-batch
// accumulators and reduces all 16 shfl chains interleaved (latency pipelined).
// ---------------------------------------------------------------------------
__global__ __launch_bounds__(256) void fc1_kernel(
    const float* __restrict__ w_reduce, const float* __restrict__ b_reduce)
{
    const int tid  = threadIdx.x;
    const int warp = tid >> 5;
    const int lane = tid & 31;

    const int j = blockIdx.x * 8 + warp;

    // ---- PDL prologue: independent of predecessor ----
    const float4* __restrict__ w =
        reinterpret_cast<const float4*>(w_reduce + (size_t)j * NC4);
    float4 wr[8];
#pragma unroll
    for (int i = 0; i < 8; ++i)
        wr[i] = w[lane + 32 * i];
    const float bj = b_reduce[j];

    // ---- wait for quad_means ----
    cudaGridDependencySynchronize();

    __shared__ float4 sm_m[NB * 256];     // all means: 16 x 1024 fp32 = 64KB
    {
        const float4* __restrict__ mp = reinterpret_cast<const float4*>(g_means);
#pragma unroll
        for (int i = 0; i < 16; ++i)
            sm_m[tid + i * 256] = mp[tid + i * 256];
    }
    __syncthreads();

    float acc[NB];
#pragma unroll
    for (int b = 0; b < NB; ++b) {
        float a = 0.f;
#pragma unroll
        for (int i = 0; i < 8; ++i) {
            float4 mv = sm_m[b * 256 + lane + 32 * i];
            a += wr[i].x * mv.x + wr[i].y * mv.y + wr[i].z * mv.z + wr[i].w * mv.w;
        }
        acc[b] = a;
    }

    // interleaved butterfly reduce: 16 independent chains pipeline the SHFL latency
#pragma unroll
    for (int o = 16; o > 0; o >>= 1) {
#pragma unroll
        for (int b = 0; b < NB; ++b)
            acc[b] += __shfl_xor_sync(0xFFFFFFFFu, acc[b], o);
    }

    if (lane == 0) {
#pragma unroll
        for (int b = 0; b < NB; ++b) {
            float x = acc[b] + bj;
            float sp = (x > 20.0f) ? x : log1pf(expf(x));
            g_z[b * NSQ + j] = x * tanhf(sp);
        }
    }
}

// ---------------------------------------------------------------------------
// Kernel 2b: gate = sigmoid(z @ w_expand^T + b_expand).
// Grid 128 x 256: warp-per-output (1024 warps), 16 per-batch accumulators,
// interleaved reduce. Weight rows loaded pre-sync (PDL prologue).
// ---------------------------------------------------------------------------
__global__ __launch_bounds__(256) void fc2_kernel(
    const float* __restrict__ w_expand, const float* __restrict__ b_expand)
{
    const int tid  = threadIdx.x;
    const int warp = tid >> 5;
    const int lane = tid & 31;

    const int j = blockIdx.x * 8 + warp;

    // ---- PDL prologue ----
    const float4* __restrict__ w =
        reinterpret_cast<const float4*>(w_expand + (size_t)j * NSQ);
    float4 w0 = w[lane];
    float4 w1 = w[lane + 32];
    const float bj = b_expand[j];

    // ---- wait for fc1 ----
    cudaGridDependencySynchronize();

    __shared__ float4 sm_z[NB * 64];      // all z: 16 x 256 fp32 = 16KB
    {
        const float4* __restrict__ zp = reinterpret_cast<const float4*>(g_z);
#pragma unroll
        for (int i = 0; i < 4; ++i)
            sm_z[tid + i * 256] = zp[tid + i * 256];
    }
    __syncthreads();

    float acc[NB];
#pragma unroll
    for (int b = 0; b < NB; ++b) {
        float4 z0 = sm_z[b * 64 + lane];
        float4 z1 = sm_z[b * 64 + lane + 32];
        acc[b] = w0.x * z0.x + w0.y * z0.y + w0.z * z0.z + w0.w * z0.w
               + w1.x * z1.x + w1.y * z1.y + w1.z * z1.z + w1.w * z1.w;
    }

#pragma unroll
    for (int o = 16; o > 0; o >>= 1) {
#pragma unroll
        for (int b = 0; b < NB; ++b)
            acc[b] += __shfl_xor_sync(0xFFFFFFFFu, acc[b], o);
    }

    if (lane == 0) {
#pragma unroll
        for (int b = 0; b < NB; ++b)
            g_gate[b * NC4 + j] = 1.0f / (1.0f + expf(-acc[b] - bj));
    }
}

// ---------------------------------------------------------------------------
// Kernel 3: out = t * gate. 4 float4 per thread. PDL: the four t loads are
// issued BEFORE the dependency sync (t doesn't depend on the gate), so
// wave-1 CTAs prefetch t while fc1/fc2 are still running.
// ---------------------------------------------------------------------------
__global__ __launch_bounds__(256) void apply_gate_kernel(
    const float* __restrict__ t, float* __restrict__ out)
{
    const int base = blockIdx.x * 1024 + threadIdx.x;   // float4 index

    const float4* __restrict__ tp = reinterpret_cast<const float4*>(t);
    float4* __restrict__ op       = reinterpret_cast<float4*>(out);

    // ---- PDL prologue: prefetch t (independent of gate) ----
    float4 v0 = __ldcs(tp + base);
    float4 v1 = __ldcs(tp + base + 256);
    float4 v2 = __ldcs(tp + base + 512);
    float4 v3 = __ldcs(tp + base + 768);

    // ---- wait for fc2 ----
    cudaGridDependencySynchronize();

    const int img    = base >> 12;
    const int within = base & (IMG_F4 - 1);
    const int row    = within >> 5;
    const int col4   = within & 31;
    const int q      = ((row >= 64) ? 2 : 0) | ((col4 >= 16) ? 1 : 0);
    const int b      = img >> 8;
    const int c      = img & 255;

    const float gv = __ldg(&g_gate[b * NC4 + q * NC + c]);

    v0.x *= gv; v0.y *= gv; v0.z *= gv; v0.w *= gv;
    v1.x *= gv; v1.y *= gv; v1.z *= gv; v1.w *= gv;
    v2.x *= gv; v2.y *= gv; v2.z *= gv; v2.w *= gv;
    v3.x *= gv; v3.y *= gv; v3.z *= gv; v3.w *= gv;

    __stcs(op + base,       v0);
    __stcs(op + base + 256, v1);
    __stcs(op + base + 512, v2);
    __stcs(op + base + 768, v3);
}

// ---------------------------------------------------------------------------
static void launch_pdl(void* func, dim3 grid, dim3 block,
                       void** args)
{
    cudaLaunchConfig_t cfg = {};
    cfg.gridDim  = grid;
    cfg.blockDim = block;
    cudaLaunchAttribute attr[1];
    attr[0].id = cudaLaunchAttributeProgrammaticStreamSerialization;
    attr[0].val.programmaticStreamSerializationAllowed = 1;
    cfg.attrs = attr;
    cfg.numAttrs = 1;
    cudaLaunchKernelExC(&cfg, func, args);
}

extern "C" void kernel_launch(void* const* d_in, const int* in_sizes, int n_in,
                              void* d_out, int out_size)
{
    const float* t        = (const float*)d_in[0];
    const float* w_reduce = (const float*)d_in[1];
    const float* b_reduce = (const float*)d_in[2];
    const float* w_expand = (const float*)d_in[3];
    const float* b_expand = (const float*)d_in[4];
    float* out            = (float*)d_out;

    // Pass 1: quadrant means (4096 CTAs) — measured 41.5us @ 82.9% DRAM
    quad_means_kernel<<<NB * NC, 256>>>(t);

    // FC chain + apply, all PDL-chained so launch gaps overlap predecessors.
    {
        void* args[] = {(void*)&w_reduce, (void*)&b_reduce};
        launch_pdl((void*)fc1_kernel, dim3(32), dim3(256), args);
    }
    {
        void* args[] = {(void*)&w_expand, (void*)&b_expand};
        launch_pdl((void*)fc2_kernel, dim3(128), dim3(256), args);
    }
    {
        void* args[] = {(void*)&t, (void*)&out};
        const int total_f4 = NB * NC * IMG_F4;   // 16777216
        dim3 grid(total_f4 / 1024);
        launch_pdl((void*)apply_gate_kernel, grid, dim3(256), args);
    }
}

// round 9
// speedup vs baseline: 1.1439x; 1.0320x over previous
#include <cuda_runtime.h>
#include <math.h>

// Problem shape (fixed by the dataset):
//   t: [16, 256, 128, 128] fp32
//   w_reduce: [256, 1024], b_reduce: [256]
//   w_expand: [1024, 256], b_expand: [1024]
// Output: same shape as t.

#define NB   16
#define NC   256
#define NSQ  256
#define NC4  1024         // 4*C
#define IMG_F4 4096       // 128*128/4 float4 per (b,c) image

// Scratch (allocation-free rule: __device__ globals)
__device__ float g_means[NB * NC4];   // layout: [b][q*C + c]
__device__ float g_z    [NB * NSQ];   // layout: [b][j]
__device__ float g_gate [NB * NC4];   // layout: [b][q*C + c]

// ---------------------------------------------------------------------------
// Kernel 1: per-(b,c) quadrant means. (Measured 41.5us @ 82.9% DRAM — keep.)
// Default (allocating) loads on purpose: the tail of t stays L2-resident for
// apply_gate's reverse-order reads.
// ---------------------------------------------------------------------------
__global__ __launch_bounds__(256) void quad_means_kernel(const float* __restrict__ t)
{
    const int img = blockIdx.x;                 // b*C + c
    const int tid = threadIdx.x;
    const float4* __restrict__ p =
        reinterpret_cast<const float4*>(t) + (size_t)img * IMG_F4;

    float topS = 0.f, botS = 0.f;
#pragma unroll
    for (int k = 0; k < 16; ++k) {
        float4 v = p[tid + k * 256];
        float s = (v.x + v.y) + (v.z + v.w);
        if (k < 8) topS += s; else botS += s;
    }

    const bool right = (tid & 31) >= 16;

    __shared__ float sm[4 * 256];
    sm[0 * 256 + tid] = right ? 0.f : topS;   // q0: top-left
    sm[1 * 256 + tid] = right ? topS : 0.f;   // q1: top-right
    sm[2 * 256 + tid] = right ? 0.f : botS;   // q2: bot-left
    sm[3 * 256 + tid] = right ? botS : 0.f;   // q3: bot-right
    __syncthreads();

#pragma unroll
    for (int st = 128; st > 0; st >>= 1) {
        if (tid < st) {
#pragma unroll
            for (int q = 0; q < 4; ++q)
                sm[q * 256 + tid] += sm[q * 256 + tid + st];
        }
        __syncthreads();
    }

    if (tid < 4) {
        const int b = img >> 8;
        const int c = img & 255;
        g_means[b * NC4 + tid * NC + c] = sm[tid * 256] * (1.0f / 4096.0f);
    }
}

// ---------------------------------------------------------------------------
// Kernel 2a: z = mish(means @ w_reduce^T + b_reduce).
// PDL: weight rows loaded into registers BEFORE the dependency sync.
// Grid 32 x 256. Warp w owns output j = cta*8 + w; 16 per-batch accumulators,
// interleaved shfl reduce.
// ---------------------------------------------------------------------------
__global__ __launch_bounds__(256) void fc1_kernel(
    const float* __restrict__ w_reduce, const float* __restrict__ b_reduce)
{
    const int tid  = threadIdx.x;
    const int warp = tid >> 5;
    const int lane = tid & 31;

    const int j = blockIdx.x * 8 + warp;

    // ---- PDL prologue: independent of predecessor ----
    const float4* __restrict__ w =
        reinterpret_cast<const float4*>(w_reduce + (size_t)j * NC4);
    float4 wr[8];
#pragma unroll
    for (int i = 0; i < 8; ++i)
        wr[i] = w[lane + 32 * i];
    const float bj = b_reduce[j];

    // ---- wait for quad_means ----
    cudaGridDependencySynchronize();

    __shared__ float4 sm_m[NB * 256];     // all means: 16 x 1024 fp32 = 64KB
    {
        const float4* __restrict__ mp = reinterpret_cast<const float4*>(g_means);
#pragma unroll
        for (int i = 0; i < 16; ++i)
            sm_m[tid + i * 256] = mp[tid + i * 256];
    }
    __syncthreads();

    float acc[NB];
#pragma unroll
    for (int b = 0; b < NB; ++b) {
        float a = 0.f;
#pragma unroll
        for (int i = 0; i < 8; ++i) {
            float4 mv = sm_m[b * 256 + lane + 32 * i];
            a += wr[i].x * mv.x + wr[i].y * mv.y + wr[i].z * mv.z + wr[i].w * mv.w;
        }
        acc[b] = a;
    }

#pragma unroll
    for (int o = 16; o > 0; o >>= 1) {
#pragma unroll
        for (int b = 0; b < NB; ++b)
            acc[b] += __shfl_xor_sync(0xFFFFFFFFu, acc[b], o);
    }

    if (lane == 0) {
#pragma unroll
        for (int b = 0; b < NB; ++b) {
            float x = acc[b] + bj;
            float sp = (x > 20.0f) ? x : log1pf(expf(x));
            g_z[b * NSQ + j] = x * tanhf(sp);
        }
    }
}

// ---------------------------------------------------------------------------
// Kernel 2b: gate = sigmoid(z @ w_expand^T + b_expand).
// Grid 128 x 256: warp-per-output, 16 per-batch accumulators, interleaved
// reduce. Weight rows loaded pre-sync (PDL prologue).
// ---------------------------------------------------------------------------
__global__ __launch_bounds__(256) void fc2_kernel(
    const float* __restrict__ w_expand, const float* __restrict__ b_expand)
{
    const int tid  = threadIdx.x;
    const int warp = tid >> 5;
    const int lane = tid & 31;

    const int j = blockIdx.x * 8 + warp;

    // ---- PDL prologue ----
    const float4* __restrict__ w =
        reinterpret_cast<const float4*>(w_expand + (size_t)j * NSQ);
    float4 w0 = w[lane];
    float4 w1 = w[lane + 32];
    const float bj = b_expand[j];

    // ---- wait for fc1 ----
    cudaGridDependencySynchronize();

    __shared__ float4 sm_z[NB * 64];      // all z: 16 x 256 fp32 = 16KB
    {
        const float4* __restrict__ zp = reinterpret_cast<const float4*>(g_z);
#pragma unroll
        for (int i = 0; i < 4; ++i)
            sm_z[tid + i * 256] = zp[tid + i * 256];
    }
    __syncthreads();

    float acc[NB];
#pragma unroll
    for (int b = 0; b < NB; ++b) {
        float4 z0 = sm_z[b * 64 + lane];
        float4 z1 = sm_z[b * 64 + lane + 32];
        acc[b] = w0.x * z0.x + w0.y * z0.y + w0.z * z0.z + w0.w * z0.w
               + w1.x * z1.x + w1.y * z1.y + w1.z * z1.z + w1.w * z1.w;
    }

#pragma unroll
    for (int o = 16; o > 0; o >>= 1) {
#pragma unroll
        for (int b = 0; b < NB; ++b)
            acc[b] += __shfl_xor_sync(0xFFFFFFFFu, acc[b], o);
    }

    if (lane == 0) {
#pragma unroll
        for (int b = 0; b < NB; ++b)
            g_gate[b * NC4 + j] = 1.0f / (1.0f + expf(-acc[b] - bj));
    }
}

// ---------------------------------------------------------------------------
// Kernel 3: out = t * gate. 4 float4 per thread. PDL prefetch of t pre-sync.
// REVERSE traversal: first waves (whose prefetch overlaps fc1/fc2) read the
// highest addresses — exactly the tail of t that quad_means left L2-resident.
// Loads default-policy (L2 hits wanted); stores streaming (evict-first) to
// limit pollution of the still-cached tail.
// ---------------------------------------------------------------------------
__global__ __launch_bounds__(256) void apply_gate_kernel(
    const float* __restrict__ t, float* __restrict__ out)
{
    const int cta  = gridDim.x - 1 - blockIdx.x;        // descending order
    const int base = cta * 1024 + threadIdx.x;          // float4 index

    const float4* __restrict__ tp = reinterpret_cast<const float4*>(t);
    float4* __restrict__ op       = reinterpret_cast<float4*>(out);

    // ---- PDL prologue: prefetch t (independent of gate) ----
    float4 v0 = tp[base];
    float4 v1 = tp[base + 256];
    float4 v2 = tp[base + 512];
    float4 v3 = tp[base + 768];

    // ---- wait for fc2 ----
    cudaGridDependencySynchronize();

    const int img    = base >> 12;
    const int within = base & (IMG_F4 - 1);
    const int row    = within >> 5;
    const int col4   = within & 31;
    const int q      = ((row >= 64) ? 2 : 0) | ((col4 >= 16) ? 1 : 0);
    const int b      = img >> 8;
    const int c      = img & 255;

    const float gv = __ldg(&g_gate[b * NC4 + q * NC + c]);

    v0.x *= gv; v0.y *= gv; v0.z *= gv; v0.w *= gv;
    v1.x *= gv; v1.y *= gv; v1.z *= gv; v1.w *= gv;
    v2.x *= gv; v2.y *= gv; v2.z *= gv; v2.w *= gv;
    v3.x *= gv; v3.y *= gv; v3.z *= gv; v3.w *= gv;

    __stcs(op + base,       v0);
    __stcs(op + base + 256, v1);
    __stcs(op + base + 512, v2);
    __stcs(op + base + 768, v3);
}

// ---------------------------------------------------------------------------
static void launch_pdl(void* func, dim3 grid, dim3 block, void** args)
{
    cudaLaunchConfig_t cfg = {};
    cfg.gridDim  = grid;
    cfg.blockDim = block;
    cudaLaunchAttribute attr[1];
    attr[0].id = cudaLaunchAttributeProgrammaticStreamSerialization;
    attr[0].val.programmaticStreamSerializationAllowed = 1;
    cfg.attrs = attr;
    cfg.numAttrs = 1;
    cudaLaunchKernelExC(&cfg, func, args);
}

extern "C" void kernel_launch(void* const* d_in, const int* in_sizes, int n_in,
                              void* d_out, int out_size)
{
    const float* t        = (const float*)d_in[0];
    const float* w_reduce = (const float*)d_in[1];
    const float* b_reduce = (const float*)d_in[2];
    const float* w_expand = (const float*)d_in[3];
    const float* b_expand = (const float*)d_in[4];
    float* out            = (float*)d_out;

    // Pass 1: quadrant means (4096 CTAs) — measured 41.5us @ 82.9% DRAM
    quad_means_kernel<<<NB * NC, 256>>>(t);

    // FC chain + apply, PDL-chained.
    {
        void* args[] = {(void*)&w_reduce, (void*)&b_reduce};
        launch_pdl((void*)fc1_kernel, dim3(32), dim3(256), args);
    }
    {
        void* args[] = {(void*)&w_expand, (void*)&b_expand};
        launch_pdl((void*)fc2_kernel, dim3(128), dim3(256), args);
    }
    {
        void* args[] = {(void*)&t, (void*)&out};
        const int total_f4 = NB * NC * IMG_F4;   // 16777216
        dim3 grid(total_f4 / 1024);
        launch_pdl((void*)apply_gate_kernel, grid, dim3(256), args);
    }
}